// round 2
// baseline (speedup 1.0000x reference)
#include <cuda_runtime.h>

#define N_NODES 100000
#define N_EDGES 1600000
#define NHEADS  4
#define HID     16
#define C1      64      // NHEADS*HID
#define NEG     0.2f

#define NB_SCAN   125   // 125 * 800 = 100000
#define CHUNK     800

// ---------------- scratch (device globals; no allocations allowed) ----------
__device__ int    g_counts[N_NODES];       // histogram, then reused as scatter cursor
__device__ int    g_rowptr[N_NODES + 1];
__device__ int    g_blockoff[NB_SCAN + 1];
__device__ int    g_csr_src[N_EDGES];
__device__ float  g_h1[N_NODES * C1];
__device__ float4 g_as1[N_NODES];          // 4 heads packed
__device__ float4 g_ad1[N_NODES];
__device__ float  g_x1[N_NODES * C1];      // relu(layer1 out)
__device__ float2 g_h2[N_NODES];
__device__ float  g_as2[N_NODES];
__device__ float  g_ad2[N_NODES];

__device__ __forceinline__ float lrelu(float x) { return x > 0.f ? x : NEG * x; }

// ---------------- CSR build --------------------------------------------------
__global__ void k_zero_counts() {
    int i = blockIdx.x * blockDim.x + threadIdx.x;
    if (i < N_NODES) g_counts[i] = 0;
}

__global__ void k_hist(const int* __restrict__ ei) {
    int e = blockIdx.x * blockDim.x + threadIdx.x;
    if (e < N_EDGES) {
        int dst = ei[N_EDGES + e];
        if ((unsigned)dst < N_NODES) atomicAdd(&g_counts[dst], 1);
    }
}

__global__ void k_scan_partial() {
    __shared__ int sh[256];
    int b = blockIdx.x, t = threadIdx.x;
    int s = 0;
    for (int i = t; i < CHUNK; i += 256) s += g_counts[b * CHUNK + i];
    sh[t] = s;
    __syncthreads();
    for (int o = 128; o > 0; o >>= 1) {
        if (t < o) sh[t] += sh[t + o];
        __syncthreads();
    }
    if (t == 0) g_blockoff[b] = sh[0];
}

__global__ void k_scan_mid() {
    if (threadIdx.x == 0) {
        int run = 0;
        for (int b = 0; b < NB_SCAN; b++) {
            int v = g_blockoff[b];
            g_blockoff[b] = run;
            run += v;
        }
        g_rowptr[N_NODES] = run;
    }
}

__global__ void k_scan_final() {   // 800 threads per block
    __shared__ int sh[CHUNK];
    int b = blockIdx.x, t = threadIdx.x;
    int idx = b * CHUNK + t;
    int v = g_counts[idx];
    sh[t] = v;
    __syncthreads();
    for (int o = 1; o < CHUNK; o <<= 1) {
        int add = (t >= o) ? sh[t - o] : 0;
        __syncthreads();
        sh[t] += add;
        __syncthreads();
    }
    g_rowptr[idx] = g_blockoff[b] + sh[t] - v;   // exclusive
    g_counts[idx] = 0;                           // becomes scatter cursor
}

__global__ void k_scatter(const int* __restrict__ ei) {
    int e = blockIdx.x * blockDim.x + threadIdx.x;
    if (e < N_EDGES) {
        int src = ei[e];
        int dst = ei[N_EDGES + e];
        if ((unsigned)src < N_NODES && (unsigned)dst < N_NODES) {
            int pos = g_rowptr[dst] + atomicAdd(&g_counts[dst], 1);
            g_csr_src[pos] = src;
        }
    }
}

// ---------------- layer 1: x@W1 (+ attention dot products) ------------------
// block = 256 threads, covers 8 nodes. Each thread: 1 channel x 2 nodes.
__global__ void k_gemm1(const float* __restrict__ x, const float* __restrict__ W1,
                        const float* __restrict__ a_src, const float* __restrict__ a_dst) {
    __shared__ float sW[64 * 64];
    __shared__ float sX[8 * 64];
    __shared__ float sH[8 * 64];
    __shared__ float sA[64], sD[64];
    int t  = threadIdx.x;
    int n0 = blockIdx.x * 8;

    const float4* W4  = (const float4*)W1;
    float4*       sW4 = (float4*)sW;
    #pragma unroll
    for (int i = 0; i < 4; i++) sW4[t + i * 256] = W4[t + i * 256];
    const float4* X4  = (const float4*)(x + (size_t)n0 * 64);
    float4*       sX4 = (float4*)sX;
    if (t < 128) sX4[t] = X4[t];
    if (t < 64) { sA[t] = a_src[t]; sD[t] = a_dst[t]; }
    __syncthreads();

    int c = t & 63;
    int g = t >> 6;            // 0..3  -> nodes g and g+4
    float acc_a = 0.f, acc_b = 0.f;
    #pragma unroll
    for (int k = 0; k < 64; k++) {
        float w = sW[k * 64 + c];
        acc_a += sX[g * 64 + k]       * w;
        acc_b += sX[(g + 4) * 64 + k] * w;
    }
    int na = n0 + g, nb = n0 + g + 4;
    g_h1[(size_t)na * 64 + c] = acc_a;
    g_h1[(size_t)nb * 64 + c] = acc_b;
    sH[g * 64 + c]       = acc_a;
    sH[(g + 4) * 64 + c] = acc_b;
    __syncthreads();

    // 8 nodes * 4 heads * {src,dst} = 64 reduction tasks
    if (t < 64) {
        int nl = t >> 3;          // node 0..7
        int hh = (t >> 1) & 3;    // head
        int wh = t & 1;           // 0 = src, 1 = dst
        const float* av = wh ? sD : sA;
        float s = 0.f;
        #pragma unroll
        for (int i = 0; i < 16; i++) s += sH[nl * 64 + hh * 16 + i] * av[hh * 16 + i];
        int n = n0 + nl;
        if (wh) ((float*)g_ad1)[n * 4 + hh] = s;
        else    ((float*)g_as1)[n * 4 + hh] = s;
    }
}

// ---------------- layer 1: softmax + aggregate (warp per dst node) ----------
__global__ void k_gather1(const float* __restrict__ bias) {
    int n = blockIdx.x * 8 + (threadIdx.x >> 5);
    if (n >= N_NODES) return;
    int lane = threadIdx.x & 31;
    int beg = g_rowptr[n], end = g_rowptr[n + 1];

    float4 adn = g_ad1[n];
    float4 asn = g_as1[n];
    float es0 = lrelu(asn.x + adn.x);
    float es1 = lrelu(asn.y + adn.y);
    float es2 = lrelu(asn.z + adn.z);
    float es3 = lrelu(asn.w + adn.w);
    float m0 = es0, m1 = es1, m2 = es2, m3 = es3;

    // pass 1: per-head max over incoming edges (lanes over edges)
    for (int j = beg + lane; j < end; j += 32) {
        int s = g_csr_src[j];
        float4 a = g_as1[s];
        m0 = fmaxf(m0, lrelu(a.x + adn.x));
        m1 = fmaxf(m1, lrelu(a.y + adn.y));
        m2 = fmaxf(m2, lrelu(a.z + adn.z));
        m3 = fmaxf(m3, lrelu(a.w + adn.w));
    }
    #pragma unroll
    for (int o = 16; o; o >>= 1) {
        m0 = fmaxf(m0, __shfl_xor_sync(0xffffffffu, m0, o));
        m1 = fmaxf(m1, __shfl_xor_sync(0xffffffffu, m1, o));
        m2 = fmaxf(m2, __shfl_xor_sync(0xffffffffu, m2, o));
        m3 = fmaxf(m3, __shfl_xor_sync(0xffffffffu, m3, o));
    }

    // pass 2 (fused): lanes over channels; accumulate sum(ex) and sum(ex*h)
    int c0 = lane, c1 = lane + 32;
    bool lo = lane < 16;
    float adh0 = lo ? adn.x : adn.y;
    float adh1 = lo ? adn.z : adn.w;
    float mh0  = lo ? m0 : m1;
    float mh1  = lo ? m2 : m3;
    float esh0 = lo ? es0 : es1;
    float esh1 = lo ? es2 : es3;
    int   h0   = lo ? 0 : 1;
    int   h1   = h0 + 2;

    float exs0 = __expf(esh0 - mh0);
    float exs1 = __expf(esh1 - mh1);
    float sum0 = exs0, sum1 = exs1;
    float acc0 = exs0 * g_h1[(size_t)n * 64 + c0];
    float acc1 = exs1 * g_h1[(size_t)n * 64 + c1];

    const float* as1f = (const float*)g_as1;
    for (int j = beg; j < end; j++) {
        int s = g_csr_src[j];                       // uniform across warp
        float e0 = as1f[s * 4 + h0] + adh0;
        float e1 = as1f[s * 4 + h1] + adh1;
        float ex0 = __expf(lrelu(e0) - mh0);
        float ex1 = __expf(lrelu(e1) - mh1);
        sum0 += ex0;
        sum1 += ex1;
        acc0 += ex0 * g_h1[(size_t)s * 64 + c0];
        acc1 += ex1 * g_h1[(size_t)s * 64 + c1];
    }
    float inv0 = 1.f / (sum0 + 1e-16f);
    float inv1 = 1.f / (sum1 + 1e-16f);
    g_x1[(size_t)n * 64 + c0] = fmaxf(acc0 * inv0 + bias[c0], 0.f);
    g_x1[(size_t)n * 64 + c1] = fmaxf(acc1 * inv1 + bias[c1], 0.f);
}

// ---------------- layer 2: x1@W2 + attention scalars (warp per node) --------
__global__ void k_gemm2(const float* __restrict__ W2, const float* __restrict__ a_src2,
                        const float* __restrict__ a_dst2) {
    int n = blockIdx.x * 8 + (threadIdx.x >> 5);
    if (n >= N_NODES) return;
    int lane = threadIdx.x & 31;
    float xa = g_x1[(size_t)n * 64 + lane];
    float xb = g_x1[(size_t)n * 64 + lane + 32];
    float p0 = xa * W2[lane * 2 + 0] + xb * W2[(lane + 32) * 2 + 0];
    float p1 = xa * W2[lane * 2 + 1] + xb * W2[(lane + 32) * 2 + 1];
    #pragma unroll
    for (int o = 16; o; o >>= 1) {
        p0 += __shfl_xor_sync(0xffffffffu, p0, o);
        p1 += __shfl_xor_sync(0xffffffffu, p1, o);
    }
    if (lane == 0) {
        g_h2[n] = make_float2(p0, p1);
        g_as2[n] = p0 * a_src2[0] + p1 * a_src2[1];
        g_ad2[n] = p0 * a_dst2[0] + p1 * a_dst2[1];
    }
}

// ---------------- layer 2: softmax + aggregate (warp per dst node) ----------
__global__ void k_gather2(float* __restrict__ out, const float* __restrict__ b2) {
    int n = blockIdx.x * 8 + (threadIdx.x >> 5);
    if (n >= N_NODES) return;
    int lane = threadIdx.x & 31;
    int beg = g_rowptr[n], end = g_rowptr[n + 1];

    float adn = g_ad2[n];
    float es  = lrelu(g_as2[n] + adn);
    float m = es;
    for (int j = beg + lane; j < end; j += 32)
        m = fmaxf(m, lrelu(g_as2[g_csr_src[j]] + adn));
    #pragma unroll
    for (int o = 16; o; o >>= 1)
        m = fmaxf(m, __shfl_xor_sync(0xffffffffu, m, o));

    float s = 0.f, a0 = 0.f, a1 = 0.f;
    if (lane == 0) {
        float exs = __expf(es - m);
        float2 hn = g_h2[n];
        s = exs; a0 = exs * hn.x; a1 = exs * hn.y;
    }
    for (int j = beg + lane; j < end; j += 32) {
        int src = g_csr_src[j];
        float ex = __expf(lrelu(g_as2[src] + adn) - m);
        float2 hv = g_h2[src];
        s  += ex;
        a0 += ex * hv.x;
        a1 += ex * hv.y;
    }
    #pragma unroll
    for (int o = 16; o; o >>= 1) {
        s  += __shfl_xor_sync(0xffffffffu, s, o);
        a0 += __shfl_xor_sync(0xffffffffu, a0, o);
        a1 += __shfl_xor_sync(0xffffffffu, a1, o);
    }
    if (lane == 0) {
        float inv = 1.f / (s + 1e-16f);
        out[n * 2 + 0] = a0 * inv + b2[0];
        out[n * 2 + 1] = a1 * inv + b2[1];
    }
}

// ---------------- launch -----------------------------------------------------
extern "C" void kernel_launch(void* const* d_in, const int* in_sizes, int n_in,
                              void* d_out, int out_size) {
    const float* x      = (const float*)d_in[0];
    const int*   ei     = (const int*)d_in[1];       // edge_index is int32 (JAX x64 disabled)
    // d_in[2] = edge_attr (ignored, matching reference)
    const float* W1     = (const float*)d_in[3];
    const float* asrc1  = (const float*)d_in[4];
    const float* adst1  = (const float*)d_in[5];
    const float* b1     = (const float*)d_in[6];
    const float* W2     = (const float*)d_in[7];
    const float* asrc2  = (const float*)d_in[8];
    const float* adst2  = (const float*)d_in[9];
    const float* b2     = (const float*)d_in[10];
    float*       out    = (float*)d_out;

    const int EB = (N_EDGES + 255) / 256;           // 6250
    const int ZB = (N_NODES + 255) / 256;           // 391
    const int WB = (N_NODES + 7) / 8;               // 12500 (8 warps/block)

    // CSR build (per launch; idempotent)
    k_zero_counts<<<ZB, 256>>>();
    k_hist<<<EB, 256>>>(ei);
    k_scan_partial<<<NB_SCAN, 256>>>();
    k_scan_mid<<<1, 32>>>();
    k_scan_final<<<NB_SCAN, CHUNK>>>();
    k_scatter<<<EB, 256>>>(ei);

    // layer 1
    k_gemm1<<<WB, 256>>>(x, W1, asrc1, adst1);
    k_gather1<<<WB, 256>>>(b1);

    // layer 2
    k_gemm2<<<WB, 256>>>(W2, asrc2, adst2);
    k_gather2<<<WB, 256>>>(out, b2);
}

// round 4
// speedup vs baseline: 1.3303x; 1.3303x over previous
#include <cuda_runtime.h>

#define N_NODES 100000
#define N_EDGES 1600000
#define C1      64
#define NEG     0.2f

#define NB_SCAN 125     // 125 * 800 = 100000
#define CHUNK   800

// ---------------- scratch (device globals; zero-initialized at load) --------
__device__ int    g_counts[N_NODES];       // hist -> deg; scatter decrements back to 0
__device__ int    g_rowptr[N_NODES + 1];
__device__ int    g_blockoff[NB_SCAN + 1];
__device__ int    g_csr_src[N_EDGES];
__device__ float  g_h1[N_NODES * C1];
__device__ float4 g_as1[N_NODES];          // 4 heads packed
__device__ float4 g_ad1[N_NODES];
__device__ float2 g_h2[N_NODES];
__device__ float  g_as2[N_NODES];
__device__ float  g_ad2[N_NODES];

__device__ __forceinline__ float lrelu(float x) { return x > 0.f ? x : NEG * x; }

// ---------------- CSR build --------------------------------------------------
__global__ void k_hist(const int* __restrict__ ei) {
    int i = blockIdx.x * blockDim.x + threadIdx.x;
    if (i < N_EDGES / 4) {
        int4 d = ((const int4*)(ei + N_EDGES))[i];
        atomicAdd(&g_counts[d.x], 1);
        atomicAdd(&g_counts[d.y], 1);
        atomicAdd(&g_counts[d.z], 1);
        atomicAdd(&g_counts[d.w], 1);
    }
}

__global__ void k_scan_partial() {
    __shared__ int sh[256];
    int b = blockIdx.x, t = threadIdx.x;
    int s = 0;
    for (int i = t; i < CHUNK; i += 256) s += g_counts[b * CHUNK + i];
    sh[t] = s;
    __syncthreads();
    for (int o = 128; o > 0; o >>= 1) {
        if (t < o) sh[t] += sh[t + o];
        __syncthreads();
    }
    if (t == 0) g_blockoff[b] = sh[0];
}

__global__ void k_scan_final() {   // 800 threads/block; fuses the mid-scan
    __shared__ int sh[CHUNK];
    __shared__ int soff[256];
    int b = blockIdx.x, t = threadIdx.x;

    // sum of g_blockoff[0..b) across 256 lanes
    if (t < 256) {
        int acc = 0;
        for (int i = t; i < b; i += 256) acc += g_blockoff[i];
        soff[t] = acc;
    }
    __syncthreads();
    for (int o = 128; o > 0; o >>= 1) {
        if (t < o) soff[t] += soff[t + o];
        __syncthreads();
    }
    int base = soff[0];

    int idx = b * CHUNK + t;
    int v = g_counts[idx];
    sh[t] = v;
    __syncthreads();
    for (int o = 1; o < CHUNK; o <<= 1) {
        int add = (t >= o) ? sh[t - o] : 0;
        __syncthreads();
        sh[t] += add;
        __syncthreads();
    }
    g_rowptr[idx] = base + sh[t] - v;          // exclusive prefix
    if (b == 0 && t == 0) g_rowptr[N_NODES] = N_EDGES;
}

__global__ void k_scatter(const int* __restrict__ ei) {
    int i = blockIdx.x * blockDim.x + threadIdx.x;
    if (i < N_EDGES / 4) {
        int4 s4 = ((const int4*)ei)[i];
        int4 d4 = ((const int4*)(ei + N_EDGES))[i];
        #pragma unroll
        for (int q = 0; q < 4; q++) {
            int src = (&s4.x)[q], dst = (&d4.x)[q];
            int old = atomicSub(&g_counts[dst], 1);   // counts return to 0 for next launch
            g_csr_src[g_rowptr[dst] + old - 1] = src;
        }
    }
}

// ---------------- layer 1: x@W1 + attention dot products --------------------
// 256 threads, 32 nodes/block. thread = (node np & np+16) x 4 channels
__global__ void k_gemm1(const float* __restrict__ x, const float* __restrict__ W1,
                        const float* __restrict__ a_src, const float* __restrict__ a_dst) {
    __shared__ float sW[64 * 64];    // sW[k][c]
    __shared__ float sX[32 * 64];
    __shared__ float sA[64], sD[64];
    int t  = threadIdx.x;
    int n0 = blockIdx.x * 32;

    float4*       sW4 = (float4*)sW;
    const float4* W4  = (const float4*)W1;
    #pragma unroll
    for (int i = 0; i < 4; i++) sW4[t + 256 * i] = W4[t + 256 * i];
    const float4* X4  = (const float4*)(x + (size_t)n0 * 64);
    float4*       sX4 = (float4*)sX;
    sX4[t] = X4[t];
    sX4[t + 256] = X4[t + 256];
    if (t < 64) { sA[t] = a_src[t]; sD[t] = a_dst[t]; }
    __syncthreads();

    int cg = t & 15;            // channels cg*4 .. cg*4+3
    int np = t >> 4;            // nodes n0+np, n0+np+16
    float4 aa = make_float4(0.f, 0.f, 0.f, 0.f);
    float4 ab = make_float4(0.f, 0.f, 0.f, 0.f);
    const float4* sWr = (const float4*)sW;
    #pragma unroll
    for (int k = 0; k < 64; k++) {
        float4 w  = sWr[k * 16 + cg];
        float  xa = sX[np * 64 + k];
        float  xb = sX[(np + 16) * 64 + k];
        aa.x += xa * w.x; aa.y += xa * w.y; aa.z += xa * w.z; aa.w += xa * w.w;
        ab.x += xb * w.x; ab.y += xb * w.y; ab.z += xb * w.z; ab.w += xb * w.w;
    }
    float4* H4 = (float4*)g_h1;
    H4[(size_t)(n0 + np) * 16 + cg]      = aa;
    H4[(size_t)(n0 + np + 16) * 16 + cg] = ab;

    // attention dots: head = cg>>2; reduce 4-channel partials over 4 lanes
    float4 s4 = ((const float4*)sA)[cg];
    float4 d4 = ((const float4*)sD)[cg];
    float pa = aa.x * s4.x + aa.y * s4.y + aa.z * s4.z + aa.w * s4.w;
    float pb = ab.x * s4.x + ab.y * s4.y + ab.z * s4.z + ab.w * s4.w;
    float qa = aa.x * d4.x + aa.y * d4.y + aa.z * d4.z + aa.w * d4.w;
    float qb = ab.x * d4.x + ab.y * d4.y + ab.z * d4.z + ab.w * d4.w;
    #pragma unroll
    for (int o = 1; o <= 2; o <<= 1) {
        pa += __shfl_xor_sync(0xffffffffu, pa, o);
        pb += __shfl_xor_sync(0xffffffffu, pb, o);
        qa += __shfl_xor_sync(0xffffffffu, qa, o);
        qb += __shfl_xor_sync(0xffffffffu, qb, o);
    }
    if ((t & 3) == 0) {
        int head = (cg >> 2);
        ((float*)g_as1)[(n0 + np) * 4 + head]      = pa;
        ((float*)g_ad1)[(n0 + np) * 4 + head]      = qa;
        ((float*)g_as1)[(n0 + np + 16) * 4 + head] = pb;
        ((float*)g_ad1)[(n0 + np + 16) * 4 + head] = qb;
    }
}

// ---------------- layer 1: softmax+aggregate, fused layer-2 linear ----------
__global__ void __launch_bounds__(256, 6)
k_gather1(const float* __restrict__ bias, const float* __restrict__ W2,
          const float* __restrict__ as2v, const float* __restrict__ ad2v) {
    int n = blockIdx.x * 8 + (threadIdx.x >> 5);
    if (n >= N_NODES) return;
    int lane = threadIdx.x & 31;
    int beg = g_rowptr[n], end = g_rowptr[n + 1];

    float4 adn = g_ad1[n];
    float4 asn = g_as1[n];
    int  c0 = lane, c1 = lane + 32;
    bool lo = lane < 16;
    float adh0 = lo ? adn.x : adn.y;
    float adh1 = lo ? adn.z : adn.w;
    int   h0   = lo ? 0 : 1;
    int   h1   = h0 + 2;

    // self-loop term (no max subtraction: logits tiny, fp32 exp safe)
    float ex0 = __expf(lo ? lrelu(asn.x + adn.x) : lrelu(asn.y + adn.y));
    float ex1 = __expf(lo ? lrelu(asn.z + adn.z) : lrelu(asn.w + adn.w));
    float sum0 = ex0, sum1 = ex1;
    float acc0 = ex0 * g_h1[(size_t)n * 64 + c0];
    float acc1 = ex1 * g_h1[(size_t)n * 64 + c1];

    const float* as1f = (const float*)g_as1;
    #pragma unroll 4
    for (int j = beg; j < end; j++) {
        int s = g_csr_src[j];
        float e0 = as1f[s * 4 + h0] + adh0;
        float e1 = as1f[s * 4 + h1] + adh1;
        float x0 = __expf(lrelu(e0));
        float x1 = __expf(lrelu(e1));
        sum0 += x0;
        sum1 += x1;
        acc0 += x0 * g_h1[(size_t)s * 64 + c0];
        acc1 += x1 * g_h1[(size_t)s * 64 + c1];
    }
    float v0 = fmaxf(acc0 / (sum0 + 1e-16f) + bias[c0], 0.f);
    float v1 = fmaxf(acc1 / (sum1 + 1e-16f) + bias[c1], 0.f);

    // fused layer-2 linear: h2[n] = x1[n] @ W2  (warp reduction)
    float p0 = v0 * W2[c0 * 2 + 0] + v1 * W2[c1 * 2 + 0];
    float p1 = v0 * W2[c0 * 2 + 1] + v1 * W2[c1 * 2 + 1];
    #pragma unroll
    for (int o = 16; o; o >>= 1) {
        p0 += __shfl_xor_sync(0xffffffffu, p0, o);
        p1 += __shfl_xor_sync(0xffffffffu, p1, o);
    }
    if (lane == 0) {
        g_h2[n]  = make_float2(p0, p1);
        g_as2[n] = p0 * as2v[0] + p1 * as2v[1];
        g_ad2[n] = p0 * ad2v[0] + p1 * ad2v[1];
    }
}

// ---------------- layer 2: softmax + aggregate (warp per dst node) ----------
__global__ void __launch_bounds__(256, 6)
k_gather2(float* __restrict__ out, const float* __restrict__ b2) {
    int n = blockIdx.x * 8 + (threadIdx.x >> 5);
    if (n >= N_NODES) return;
    int lane = threadIdx.x & 31;
    int beg = g_rowptr[n], end = g_rowptr[n + 1];

    float adn = g_ad2[n];
    float s = 0.f, a0 = 0.f, a1 = 0.f;
    if (lane == 0) {                                  // self loop
        float exs = __expf(lrelu(g_as2[n] + adn));
        float2 hn = g_h2[n];
        s = exs; a0 = exs * hn.x; a1 = exs * hn.y;
    }
    for (int j = beg + lane; j < end; j += 32) {
        int src = g_csr_src[j];
        float ex = __expf(lrelu(g_as2[src] + adn));
        float2 hv = g_h2[src];
        s  += ex;
        a0 += ex * hv.x;
        a1 += ex * hv.y;
    }
    #pragma unroll
    for (int o = 16; o; o >>= 1) {
        s  += __shfl_xor_sync(0xffffffffu, s, o);
        a0 += __shfl_xor_sync(0xffffffffu, a0, o);
        a1 += __shfl_xor_sync(0xffffffffu, a1, o);
    }
    if (lane == 0) {
        float inv = 1.f / (s + 1e-16f);
        out[n * 2 + 0] = a0 * inv + b2[0];
        out[n * 2 + 1] = a1 * inv + b2[1];
    }
}

// ---------------- launch -----------------------------------------------------
extern "C" void kernel_launch(void* const* d_in, const int* in_sizes, int n_in,
                              void* d_out, int out_size) {
    const float* x      = (const float*)d_in[0];
    const int*   ei     = (const int*)d_in[1];       // int32 (JAX x64 disabled)
    const float* W1     = (const float*)d_in[3];
    const float* asrc1  = (const float*)d_in[4];
    const float* adst1  = (const float*)d_in[5];
    const float* b1     = (const float*)d_in[6];
    const float* W2     = (const float*)d_in[7];
    const float* asrc2  = (const float*)d_in[8];
    const float* adst2  = (const float*)d_in[9];
    const float* b2     = (const float*)d_in[10];
    float*       out    = (float*)d_out;

    const int EB4 = (N_EDGES / 4 + 255) / 256;      // 1563
    const int WB  = (N_NODES + 7) / 8;              // 12500
    const int GB  = (N_NODES + 31) / 32;            // 3125

    // CSR build (counts buffer self-restores to zero via atomicSub in scatter)
    k_hist<<<EB4, 256>>>(ei);
    k_scan_partial<<<NB_SCAN, 256>>>();
    k_scan_final<<<NB_SCAN, CHUNK>>>();
    k_scatter<<<EB4, 256>>>(ei);

    // layer 1 (+ fused layer-2 linear)
    k_gemm1<<<GB, 256>>>(x, W1, asrc1, adst1);
    k_gather1<<<WB, 256>>>(b1, W2, asrc2, adst2);

    // layer 2 aggregation
    k_gather2<<<WB, 256>>>(out, b2);
}

// round 6
// speedup vs baseline: 1.3590x; 1.0215x over previous
#include <cuda_runtime.h>
#include <cuda_fp16.h>

#define N_NODES 100000
#define N_EDGES 1600000
#define C1      64
#define NEG     0.2f

#define NB_SCAN 125     // 125 * 800 = 100000
#define CHUNK   800

// ---------------- scratch (device globals; zero-initialized at load) --------
__device__ int    g_counts[N_NODES];       // hist -> deg; scatter decrements back to 0
__device__ int    g_rowptr[N_NODES + 1];
__device__ int    g_blockoff[NB_SCAN + 1];
__device__ int    g_esrc[N_EDGES];         // CSR src index per slot
__device__ float4 g_ew[N_EDGES];           // per-edge softmax weights, 4 heads
__device__ __half g_h1h[(size_t)N_NODES * C1];  // layer-1 features, fp16
__device__ float4 g_as1[N_NODES];          // 4 heads packed
__device__ float4 g_ad1[N_NODES];
__device__ float4 g_p2[N_NODES];           // {h2.x, h2.y, as2, ad2}

__device__ __forceinline__ float lrelu(float x) { return x > 0.f ? x : NEG * x; }

// ---------------- CSR build --------------------------------------------------
__global__ void k_hist(const int* __restrict__ ei) {
    int i = blockIdx.x * blockDim.x + threadIdx.x;
    if (i < N_EDGES / 4) {
        int4 d = ((const int4*)(ei + N_EDGES))[i];
        atomicAdd(&g_counts[d.x], 1);
        atomicAdd(&g_counts[d.y], 1);
        atomicAdd(&g_counts[d.z], 1);
        atomicAdd(&g_counts[d.w], 1);
    }
}

__global__ void k_scan_partial() {
    __shared__ int sh[256];
    int b = blockIdx.x, t = threadIdx.x;
    int s = 0;
    for (int i = t; i < CHUNK; i += 256) s += g_counts[b * CHUNK + i];
    sh[t] = s;
    __syncthreads();
    for (int o = 128; o > 0; o >>= 1) {
        if (t < o) sh[t] += sh[t + o];
        __syncthreads();
    }
    if (t == 0) g_blockoff[b] = sh[0];
}

__global__ void k_scan_final() {   // 800 threads/block; fuses the mid-scan
    __shared__ int sh[CHUNK];
    __shared__ int soff[256];
    int b = blockIdx.x, t = threadIdx.x;

    if (t < 256) {
        int acc = 0;
        for (int i = t; i < b; i += 256) acc += g_blockoff[i];
        soff[t] = acc;
    }
    __syncthreads();
    for (int o = 128; o > 0; o >>= 1) {
        if (t < o) soff[t] += soff[t + o];
        __syncthreads();
    }
    int base = soff[0];

    int idx = b * CHUNK + t;
    int v = g_counts[idx];
    sh[t] = v;
    __syncthreads();
    for (int o = 1; o < CHUNK; o <<= 1) {
        int add = (t >= o) ? sh[t - o] : 0;
        __syncthreads();
        sh[t] += add;
        __syncthreads();
    }
    g_rowptr[idx] = base + sh[t] - v;
    if (b == 0 && t == 0) g_rowptr[N_NODES] = N_EDGES;
}

// scatter + per-edge attention weight precompute (runs AFTER k_gemm1)
__global__ void k_scatter(const int* __restrict__ ei) {
    int i = blockIdx.x * blockDim.x + threadIdx.x;
    if (i < N_EDGES / 4) {
        int4 s4 = ((const int4*)ei)[i];
        int4 d4 = ((const int4*)(ei + N_EDGES))[i];
        #pragma unroll
        for (int q = 0; q < 4; q++) {
            int src = (&s4.x)[q], dst = (&d4.x)[q];
            int old = atomicSub(&g_counts[dst], 1);   // counts return to 0 each launch
            int pos = g_rowptr[dst] + old - 1;
            float4 as = g_as1[src];
            float4 ad = g_ad1[dst];
            float4 w;
            w.x = __expf(lrelu(as.x + ad.x));
            w.y = __expf(lrelu(as.y + ad.y));
            w.z = __expf(lrelu(as.z + ad.z));
            w.w = __expf(lrelu(as.w + ad.w));
            g_ew[pos]   = w;
            g_esrc[pos] = src;
        }
    }
}

// ---------------- layer 1: x@W1 + attention dot products --------------------
// 256 threads, 32 nodes/block. thread = (node np & np+16) x 4 channels
__global__ void k_gemm1(const float* __restrict__ x, const float* __restrict__ W1,
                        const float* __restrict__ a_src, const float* __restrict__ a_dst) {
    __shared__ float sW[64 * 64];    // sW[k][c]
    __shared__ float sX[32 * 64];
    __shared__ float sA[64], sD[64];
    int t  = threadIdx.x;
    int n0 = blockIdx.x * 32;

    float4*       sW4 = (float4*)sW;
    const float4* W4  = (const float4*)W1;
    #pragma unroll
    for (int i = 0; i < 4; i++) sW4[t + 256 * i] = W4[t + 256 * i];
    const float4* X4  = (const float4*)(x + (size_t)n0 * 64);
    float4*       sX4 = (float4*)sX;
    sX4[t] = X4[t];
    sX4[t + 256] = X4[t + 256];
    if (t < 64) { sA[t] = a_src[t]; sD[t] = a_dst[t]; }
    __syncthreads();

    int cg = t & 15;            // channels cg*4 .. cg*4+3
    int np = t >> 4;            // nodes n0+np, n0+np+16
    float4 aa = make_float4(0.f, 0.f, 0.f, 0.f);
    float4 ab = make_float4(0.f, 0.f, 0.f, 0.f);
    const float4* sWr = (const float4*)sW;
    #pragma unroll
    for (int k = 0; k < 64; k++) {
        float4 w  = sWr[k * 16 + cg];
        float  xa = sX[np * 64 + k];
        float  xb = sX[(np + 16) * 64 + k];
        aa.x += xa * w.x; aa.y += xa * w.y; aa.z += xa * w.z; aa.w += xa * w.w;
        ab.x += xb * w.x; ab.y += xb * w.y; ab.z += xb * w.z; ab.w += xb * w.w;
    }
    // fp16 feature store (4 halves = 8B per node per thread)
    union { uint2 u; __half2 h[2]; } pa, pb;
    pa.h[0] = __floats2half2_rn(aa.x, aa.y);
    pa.h[1] = __floats2half2_rn(aa.z, aa.w);
    pb.h[0] = __floats2half2_rn(ab.x, ab.y);
    pb.h[1] = __floats2half2_rn(ab.z, ab.w);
    ((uint2*)g_h1h)[(size_t)(n0 + np) * 16 + cg]      = pa.u;
    ((uint2*)g_h1h)[(size_t)(n0 + np + 16) * 16 + cg] = pb.u;

    // attention dots: head = cg>>2; reduce 4-channel partials over 4 lanes
    float4 s4v = ((const float4*)sA)[cg];
    float4 d4v = ((const float4*)sD)[cg];
    float paf = aa.x * s4v.x + aa.y * s4v.y + aa.z * s4v.z + aa.w * s4v.w;
    float pbf = ab.x * s4v.x + ab.y * s4v.y + ab.z * s4v.z + ab.w * s4v.w;
    float qaf = aa.x * d4v.x + aa.y * d4v.y + aa.z * d4v.z + aa.w * d4v.w;
    float qbf = ab.x * d4v.x + ab.y * d4v.y + ab.z * d4v.z + ab.w * d4v.w;
    #pragma unroll
    for (int o = 1; o <= 2; o <<= 1) {
        paf += __shfl_xor_sync(0xffffffffu, paf, o);
        pbf += __shfl_xor_sync(0xffffffffu, pbf, o);
        qaf += __shfl_xor_sync(0xffffffffu, qaf, o);
        qbf += __shfl_xor_sync(0xffffffffu, qbf, o);
    }
    if ((t & 3) == 0) {
        int head = (cg >> 2);
        ((float*)g_as1)[(n0 + np) * 4 + head]      = paf;
        ((float*)g_ad1)[(n0 + np) * 4 + head]      = qaf;
        ((float*)g_as1)[(n0 + np + 16) * 4 + head] = pbf;
        ((float*)g_ad1)[(n0 + np + 16) * 4 + head] = qbf;
    }
}

// ---------------- layer 1: aggregate (weights precomputed), fused layer-2 ---
// warp per node; lane handles channels {2*lane, 2*lane+1}; head = lane>>3
__global__ void __launch_bounds__(256, 6)
k_gather1(const float* __restrict__ bias, const float* __restrict__ W2,
          const float* __restrict__ as2v, const float* __restrict__ ad2v) {
    int n = blockIdx.x * 8 + (threadIdx.x >> 5);
    if (n >= N_NODES) return;
    int lane = threadIdx.x & 31;
    int beg = g_rowptr[n], end = g_rowptr[n + 1];

    float4 asn = g_as1[n];
    float4 adn = g_ad1[n];
    float ash = (lane < 8) ? asn.x : (lane < 16) ? asn.y : (lane < 24) ? asn.z : asn.w;
    float adh = (lane < 8) ? adn.x : (lane < 16) ? adn.y : (lane < 24) ? adn.z : adn.w;

    // self loop (no max subtraction: logits tiny, fp32 exp safe)
    float exs = __expf(lrelu(ash + adh));
    float2 hn = __half22float2(((const __half2*)g_h1h)[(size_t)n * 32 + lane]);
    float sum = exs;
    float a0 = exs * hn.x, a1 = exs * hn.y;

    #pragma unroll 4
    for (int j = beg; j < end; j++) {
        int s = g_esrc[j];                                  // broadcast
        float4 w4 = g_ew[j];                                // broadcast, 1 sector
        float w = (lane < 8) ? w4.x : (lane < 16) ? w4.y : (lane < 24) ? w4.z : w4.w;
        float2 hv = __half22float2(((const __half2*)g_h1h)[(size_t)s * 32 + lane]);
        sum += w;
        a0 += w * hv.x;
        a1 += w * hv.y;
    }
    int c0 = lane * 2, c1 = lane * 2 + 1;
    float inv = 1.f / (sum + 1e-16f);
    float v0 = fmaxf(a0 * inv + bias[c0], 0.f);
    float v1 = fmaxf(a1 * inv + bias[c1], 0.f);

    // fused layer-2 linear: h2[n] = x1[n] @ W2  (warp reduction)
    float p0 = v0 * W2[c0 * 2 + 0] + v1 * W2[c1 * 2 + 0];
    float p1 = v0 * W2[c0 * 2 + 1] + v1 * W2[c1 * 2 + 1];
    #pragma unroll
    for (int o = 16; o; o >>= 1) {
        p0 += __shfl_xor_sync(0xffffffffu, p0, o);
        p1 += __shfl_xor_sync(0xffffffffu, p1, o);
    }
    if (lane == 0) {
        float4 pk;
        pk.x = p0;
        pk.y = p1;
        pk.z = p0 * as2v[0] + p1 * as2v[1];   // as2
        pk.w = p0 * ad2v[0] + p1 * ad2v[1];   // ad2
        g_p2[n] = pk;
    }
}

// ---------------- layer 2: softmax + aggregate (warp per dst node) ----------
__global__ void __launch_bounds__(256, 6)
k_gather2(float* __restrict__ out, const float* __restrict__ b2) {
    int n = blockIdx.x * 8 + (threadIdx.x >> 5);
    if (n >= N_NODES) return;
    int lane = threadIdx.x & 31;
    int beg = g_rowptr[n], end = g_rowptr[n + 1];

    float4 pn = g_p2[n];        // {h2.x, h2.y, as2, ad2}
    float adn = pn.w;

    // self loop folded into lane 0's accumulators before the reduction
    float exl = __expf(lrelu(pn.z + adn));
    float use = (lane == 0) ? 1.f : 0.f;
    float s  = use * exl;
    float a0 = use * exl * pn.x;
    float a1 = use * exl * pn.y;

    for (int j = beg + lane; j < end; j += 32) {
        float4 ps = g_p2[g_esrc[j]];                  // one 16B load per edge
        float ex = __expf(lrelu(ps.z + adn));
        s  += ex;
        a0 += ex * ps.x;
        a1 += ex * ps.y;
    }
    #pragma unroll
    for (int o = 16; o; o >>= 1) {
        s  += __shfl_xor_sync(0xffffffffu, s, o);
        a0 += __shfl_xor_sync(0xffffffffu, a0, o);
        a1 += __shfl_xor_sync(0xffffffffu, a1, o);
    }
    if (lane == 0) {
        float inv = 1.f / (s + 1e-16f);
        out[n * 2 + 0] = a0 * inv + b2[0];
        out[n * 2 + 1] = a1 * inv + b2[1];
    }
}

// ---------------- launch -----------------------------------------------------
extern "C" void kernel_launch(void* const* d_in, const int* in_sizes, int n_in,
                              void* d_out, int out_size) {
    const float* x      = (const float*)d_in[0];
    const int*   ei     = (const int*)d_in[1];       // int32 (JAX x64 disabled)
    const float* W1     = (const float*)d_in[3];
    const float* asrc1  = (const float*)d_in[4];
    const float* adst1  = (const float*)d_in[5];
    const float* b1     = (const float*)d_in[6];
    const float* W2     = (const float*)d_in[7];
    const float* asrc2  = (const float*)d_in[8];
    const float* adst2  = (const float*)d_in[9];
    const float* b2     = (const float*)d_in[10];
    float*       out    = (float*)d_out;

    const int EB4 = (N_EDGES / 4 + 255) / 256;      // 1563
    const int WB  = (N_NODES + 7) / 8;              // 12500
    const int GB  = (N_NODES + 31) / 32;            // 3125

    // gemm1 first: scatter needs as1/ad1 to fuse the edge-weight precompute
    k_gemm1<<<GB, 256>>>(x, W1, asrc1, adst1);

    // CSR build (counts self-restore to zero via atomicSub in scatter)
    k_hist<<<EB4, 256>>>(ei);
    k_scan_partial<<<NB_SCAN, 256>>>();
    k_scan_final<<<NB_SCAN, CHUNK>>>();
    k_scatter<<<EB4, 256>>>(ei);

    // layer 1 aggregation (+ fused layer-2 linear)
    k_gather1<<<WB, 256>>>(b1, W2, asrc2, adst2);

    // layer 2 aggregation
    k_gather2<<<WB, 256>>>(out, b2);
}

// round 7
// speedup vs baseline: 1.4534x; 1.0695x over previous
#include <cuda_runtime.h>
#include <cuda_fp16.h>

#define N_NODES 100000
#define N_EDGES 1600000
#define C1      64
#define NEG     0.2f

#define NB_SCAN 125     // 125 * 800 = 100000
#define CHUNK   800

#define GB  3125        // gemm blocks (32 nodes each)
#define EB4 1563        // edge blocks (1024 edges each)

// ---------------- scratch (device globals; zero-initialized at load) --------
__device__ int    g_counts[N_NODES];       // hist -> deg; scatter decrements back to 0
__device__ int    g_rowptr[N_NODES + 1];
__device__ int    g_blockoff[NB_SCAN + 1];
__device__ int    g_esrc[N_EDGES];         // CSR src index per slot
__device__ __half g_h1h[(size_t)N_NODES * C1];  // layer-1 features, fp16
__device__ float4 g_as1[N_NODES];          // 4 heads packed
__device__ float4 g_ad1[N_NODES];
__device__ float4 g_p2[N_NODES];           // {h2.x, h2.y, as2, ad2}

__device__ __forceinline__ float lrelu(float x) { return x > 0.f ? x : NEG * x; }

// ---------------- fused: layer-1 GEMM + degree histogram ---------------------
// blocks [0, GB): gemm on 32 nodes; blocks [GB, GB+EB4): histogram on 1024 edges
__global__ void k_gemm1_hist(const float* __restrict__ x, const float* __restrict__ W1,
                             const float* __restrict__ a_src, const float* __restrict__ a_dst,
                             const int* __restrict__ ei) {
    __shared__ float sW[64 * 64];    // sW[k][c]
    __shared__ float sX[32 * 64];
    __shared__ float sA[64], sD[64];
    int t = threadIdx.x;

    if (blockIdx.x >= GB) {          // ---- histogram path ----
        int i = (blockIdx.x - GB) * 256 + t;
        if (i < N_EDGES / 4) {
            int4 d = ((const int4*)(ei + N_EDGES))[i];
            atomicAdd(&g_counts[d.x], 1);
            atomicAdd(&g_counts[d.y], 1);
            atomicAdd(&g_counts[d.z], 1);
            atomicAdd(&g_counts[d.w], 1);
        }
        return;
    }

    // ---- gemm path: 32 nodes, thread = (node np & np+16) x 4 channels ----
    int n0 = blockIdx.x * 32;
    float4*       sW4 = (float4*)sW;
    const float4* W4  = (const float4*)W1;
    #pragma unroll
    for (int i = 0; i < 4; i++) sW4[t + 256 * i] = W4[t + 256 * i];
    const float4* X4  = (const float4*)(x + (size_t)n0 * 64);
    float4*       sX4 = (float4*)sX;
    sX4[t] = X4[t];
    sX4[t + 256] = X4[t + 256];
    if (t < 64) { sA[t] = a_src[t]; sD[t] = a_dst[t]; }
    __syncthreads();

    int cg = t & 15;            // channels cg*4 .. cg*4+3
    int np = t >> 4;            // nodes n0+np, n0+np+16
    float4 aa = make_float4(0.f, 0.f, 0.f, 0.f);
    float4 ab = make_float4(0.f, 0.f, 0.f, 0.f);
    const float4* sWr = (const float4*)sW;
    #pragma unroll
    for (int k = 0; k < 64; k++) {
        float4 w  = sWr[k * 16 + cg];
        float  xa = sX[np * 64 + k];
        float  xb = sX[(np + 16) * 64 + k];
        aa.x += xa * w.x; aa.y += xa * w.y; aa.z += xa * w.z; aa.w += xa * w.w;
        ab.x += xb * w.x; ab.y += xb * w.y; ab.z += xb * w.z; ab.w += xb * w.w;
    }
    // fp16 feature store (4 halves = 8B per node per thread)
    union { uint2 u; __half2 h[2]; } pa, pb;
    pa.h[0] = __floats2half2_rn(aa.x, aa.y);
    pa.h[1] = __floats2half2_rn(aa.z, aa.w);
    pb.h[0] = __floats2half2_rn(ab.x, ab.y);
    pb.h[1] = __floats2half2_rn(ab.z, ab.w);
    ((uint2*)g_h1h)[(size_t)(n0 + np) * 16 + cg]      = pa.u;
    ((uint2*)g_h1h)[(size_t)(n0 + np + 16) * 16 + cg] = pb.u;

    // attention dots: head = cg>>2; reduce 4-channel partials over 4 lanes
    float4 s4v = ((const float4*)sA)[cg];
    float4 d4v = ((const float4*)sD)[cg];
    float paf = aa.x * s4v.x + aa.y * s4v.y + aa.z * s4v.z + aa.w * s4v.w;
    float pbf = ab.x * s4v.x + ab.y * s4v.y + ab.z * s4v.z + ab.w * s4v.w;
    float qaf = aa.x * d4v.x + aa.y * d4v.y + aa.z * d4v.z + aa.w * d4v.w;
    float qbf = ab.x * d4v.x + ab.y * d4v.y + ab.z * d4v.z + ab.w * d4v.w;
    #pragma unroll
    for (int o = 1; o <= 2; o <<= 1) {
        paf += __shfl_xor_sync(0xffffffffu, paf, o);
        pbf += __shfl_xor_sync(0xffffffffu, pbf, o);
        qaf += __shfl_xor_sync(0xffffffffu, qaf, o);
        qbf += __shfl_xor_sync(0xffffffffu, qbf, o);
    }
    if ((t & 3) == 0) {
        int head = (cg >> 2);
        ((float*)g_as1)[(n0 + np) * 4 + head]      = paf;
        ((float*)g_ad1)[(n0 + np) * 4 + head]      = qaf;
        ((float*)g_as1)[(n0 + np + 16) * 4 + head] = pbf;
        ((float*)g_ad1)[(n0 + np + 16) * 4 + head] = qbf;
    }
}

// ---------------- CSR scan ----------------------------------------------------
__global__ void k_scan_partial() {
    __shared__ int sh[256];
    int b = blockIdx.x, t = threadIdx.x;
    int s = 0;
    for (int i = t; i < CHUNK; i += 256) s += g_counts[b * CHUNK + i];
    sh[t] = s;
    __syncthreads();
    for (int o = 128; o > 0; o >>= 1) {
        if (t < o) sh[t] += sh[t + o];
        __syncthreads();
    }
    if (t == 0) g_blockoff[b] = sh[0];
}

__global__ void k_scan_final() {   // 800 threads = 25 warps; warp-shuffle scan
    __shared__ int sbase;
    __shared__ int swsum[25];
    __shared__ int swoff[25];
    int b = blockIdx.x, t = threadIdx.x;
    int lane = t & 31, wid = t >> 5;

    if (t < 32) {                                   // base = sum blockoff[0..b)
        int acc = 0;
        for (int i = t; i < b; i += 32) acc += g_blockoff[i];
        #pragma unroll
        for (int o = 16; o; o >>= 1) acc += __shfl_xor_sync(0xffffffffu, acc, o);
        if (t == 0) sbase = acc;
    }

    int idx = b * CHUNK + t;
    int v = g_counts[idx];
    int inc = v;                                    // warp inclusive scan
    #pragma unroll
    for (int o = 1; o < 32; o <<= 1) {
        int u = __shfl_up_sync(0xffffffffu, inc, o);
        if (lane >= o) inc += u;
    }
    if (lane == 31) swsum[wid] = inc;
    __syncthreads();
    if (t < 32) {                                   // scan the 25 warp sums
        int val = (t < 25) ? swsum[t] : 0;
        int in2 = val;
        #pragma unroll
        for (int o = 1; o < 32; o <<= 1) {
            int u = __shfl_up_sync(0xffffffffu, in2, o);
            if (lane >= o) in2 += u;
        }
        if (t < 25) swoff[t] = in2 - val;           // exclusive
    }
    __syncthreads();
    g_rowptr[idx] = sbase + swoff[wid] + inc - v;   // exclusive prefix
    if (b == 0 && t == 0) g_rowptr[N_NODES] = N_EDGES;
}

__global__ void k_scatter(const int* __restrict__ ei) {
    int i = blockIdx.x * blockDim.x + threadIdx.x;
    if (i < N_EDGES / 4) {
        int4 s4 = ((const int4*)ei)[i];
        int4 d4 = ((const int4*)(ei + N_EDGES))[i];
        #pragma unroll
        for (int q = 0; q < 4; q++) {
            int src = (&s4.x)[q], dst = (&d4.x)[q];
            int old = atomicSub(&g_counts[dst], 1);   // counts return to 0 each launch
            g_esrc[g_rowptr[dst] + old - 1] = src;
        }
    }
}

// ---------------- layer 1: softmax+aggregate, fused layer-2 linear ----------
// warp per node; lane handles channels {2*lane, 2*lane+1}; head = lane>>3
__global__ void __launch_bounds__(256, 6)
k_gather1(const float* __restrict__ bias, const float* __restrict__ W2,
          const float* __restrict__ as2v, const float* __restrict__ ad2v) {
    int n = blockIdx.x * 8 + (threadIdx.x >> 5);
    if (n >= N_NODES) return;
    int lane = threadIdx.x & 31;
    int beg = g_rowptr[n], end = g_rowptr[n + 1];

    float4 asn = g_as1[n];
    float4 adn = g_ad1[n];
    float ash = (lane < 8) ? asn.x : (lane < 16) ? asn.y : (lane < 24) ? asn.z : asn.w;
    float adh = (lane < 8) ? adn.x : (lane < 16) ? adn.y : (lane < 24) ? adn.z : adn.w;

    // self loop (no max subtraction: logits tiny, fp32 exp safe)
    float exs = __expf(lrelu(ash + adh));
    float2 hn = __half22float2(((const __half2*)g_h1h)[(size_t)n * 32 + lane]);
    float sum = exs;
    float a0 = exs * hn.x, a1 = exs * hn.y;

    #pragma unroll 4
    for (int j = beg; j < end; j++) {
        int s = g_esrc[j];                                  // broadcast
        float4 a = g_as1[s];                                // broadcast, 1 sector
        float av = (lane < 8) ? a.x : (lane < 16) ? a.y : (lane < 24) ? a.z : a.w;
        float w = __expf(lrelu(av + adh));
        float2 hv = __half22float2(((const __half2*)g_h1h)[(size_t)s * 32 + lane]);
        sum += w;
        a0 += w * hv.x;
        a1 += w * hv.y;
    }
    int c0 = lane * 2, c1 = lane * 2 + 1;
    float inv = 1.f / (sum + 1e-16f);
    float v0 = fmaxf(a0 * inv + bias[c0], 0.f);
    float v1 = fmaxf(a1 * inv + bias[c1], 0.f);

    // fused layer-2 linear: h2[n] = x1[n] @ W2  (warp reduction)
    float p0 = v0 * W2[c0 * 2 + 0] + v1 * W2[c1 * 2 + 0];
    float p1 = v0 * W2[c0 * 2 + 1] + v1 * W2[c1 * 2 + 1];
    #pragma unroll
    for (int o = 16; o; o >>= 1) {
        p0 += __shfl_xor_sync(0xffffffffu, p0, o);
        p1 += __shfl_xor_sync(0xffffffffu, p1, o);
    }
    if (lane == 0) {
        float4 pk;
        pk.x = p0;
        pk.y = p1;
        pk.z = p0 * as2v[0] + p1 * as2v[1];   // as2
        pk.w = p0 * ad2v[0] + p1 * ad2v[1];   // ad2
        g_p2[n] = pk;
    }
}

// ---------------- layer 2: softmax + aggregate (warp per dst node) ----------
__global__ void __launch_bounds__(256, 6)
k_gather2(float* __restrict__ out, const float* __restrict__ b2) {
    int n = blockIdx.x * 8 + (threadIdx.x >> 5);
    if (n >= N_NODES) return;
    int lane = threadIdx.x & 31;
    int beg = g_rowptr[n], end = g_rowptr[n + 1];

    float4 pn = g_p2[n];        // {h2.x, h2.y, as2, ad2}
    float adn = pn.w;

    float exl = __expf(lrelu(pn.z + adn));      // self loop on lane 0
    float use = (lane == 0) ? 1.f : 0.f;
    float s  = use * exl;
    float a0 = use * exl * pn.x;
    float a1 = use * exl * pn.y;

    for (int j = beg + lane; j < end; j += 32) {
        float4 ps = g_p2[g_esrc[j]];                  // one 16B load per edge
        float ex = __expf(lrelu(ps.z + adn));
        s  += ex;
        a0 += ex * ps.x;
        a1 += ex * ps.y;
    }
    #pragma unroll
    for (int o = 16; o; o >>= 1) {
        s  += __shfl_xor_sync(0xffffffffu, s, o);
        a0 += __shfl_xor_sync(0xffffffffu, a0, o);
        a1 += __shfl_xor_sync(0xffffffffu, a1, o);
    }
    if (lane == 0) {
        float inv = 1.f / (s + 1e-16f);
        out[n * 2 + 0] = a0 * inv + b2[0];
        out[n * 2 + 1] = a1 * inv + b2[1];
    }
}

// ---------------- launch -----------------------------------------------------
extern "C" void kernel_launch(void* const* d_in, const int* in_sizes, int n_in,
                              void* d_out, int out_size) {
    const float* x      = (const float*)d_in[0];
    const int*   ei     = (const int*)d_in[1];       // int32 (JAX x64 disabled)
    const float* W1     = (const float*)d_in[3];
    const float* asrc1  = (const float*)d_in[4];
    const float* adst1  = (const float*)d_in[5];
    const float* b1     = (const float*)d_in[6];
    const float* W2     = (const float*)d_in[7];
    const float* asrc2  = (const float*)d_in[8];
    const float* adst2  = (const float*)d_in[9];
    const float* b2     = (const float*)d_in[10];
    float*       out    = (float*)d_out;

    const int WB = (N_NODES + 7) / 8;               // 12500

    // fused layer-1 GEMM + degree histogram (independent work, one launch)
    k_gemm1_hist<<<GB + EB4, 256>>>(x, W1, asrc1, adst1, ei);

    // CSR scan + scatter (counts self-restore to zero via atomicSub)
    k_scan_partial<<<NB_SCAN, 256>>>();
    k_scan_final<<<NB_SCAN, CHUNK>>>();
    k_scatter<<<EB4, 256>>>(ei);

    // layer 1 aggregation (+ fused layer-2 linear)
    k_gather1<<<WB, 256>>>(b1, W2, asrc2, adst2);

    // layer 2 aggregation
    k_gather2<<<WB, 256>>>(out, b2);
}